// round 16
// baseline (speedup 1.0000x reference)
#include <cuda_runtime.h>
#include <cuda_fp16.h>
#include <cuda_bf16.h>
#include <cstdint>

#define NN 100000
#define NE 3200000
#define HD 128
#define EPSV 1e-5f
#define NSCANB 98   // ceil(NN/1024)

// ------------------------- device scratch (no allocs allowed) -------------------------
__device__ float  g_B0[NN * HD];      // x / layer output ping
__device__ float  g_B1[NN * HD];      // layer output pong
__device__ __half g_Hh[NN * HD];      // h = relu(x@Wt+bt) in fp16 (SpMM operand)
__device__ float  g_M[NN * HD];       // aggregated messages
__device__ int    g_rowptr[NN + 1];
__device__ int    g_cursor[NN];
__device__ int    g_cnt[NN];
__device__ float  g_deg[NN];          // weighted degree, then inv-degree (in place)
__device__ int    g_ec[NE];           // CSR column indices
__device__ float  g_ewn[NE];          // CSR normalized weights (w_e * invdeg[row])
__device__ int    g_part[128];        // scan partials
// column stats: [0:128) sum, [128:256) sumsq. [0..2]=cg layer i, [3..4]=gn layer i
__device__ float  g_stat[5][256];
// split-bf16 weights, [n][k] layout: 9 matrices (Wt x3, then (Wc[i] op-half) x6)
__device__ __nv_bfloat16 g_Bhi[9 * 16384];
__device__ __nv_bfloat16 g_Blo[9 * 16384];

// ------------------------- helpers -------------------------
__device__ __forceinline__ uint32_t smem_u32(const void* p) {
    uint32_t a;
    asm("{ .reg .u64 t; cvta.to.shared.u64 t, %1; cvt.u32.u64 %0, t; }" : "=r"(a) : "l"(p));
    return a;
}
__device__ __forceinline__ void ldsm4(uint32_t* r, uint32_t addr) {
    asm volatile("ldmatrix.sync.aligned.m8n8.x4.shared.b16 {%0,%1,%2,%3}, [%4];"
                 : "=r"(r[0]), "=r"(r[1]), "=r"(r[2]), "=r"(r[3]) : "r"(addr));
}
__device__ __forceinline__ void mma16816(float* c, const uint32_t* a, uint32_t b0,
                                         uint32_t b1) {
    asm volatile(
        "mma.sync.aligned.m16n8k16.row.col.f32.bf16.bf16.f32 "
        "{%0,%1,%2,%3}, {%4,%5,%6,%7}, {%8,%9}, {%0,%1,%2,%3};"
        : "+f"(c[0]), "+f"(c[1]), "+f"(c[2]), "+f"(c[3])
        : "r"(a[0]), "r"(a[1]), "r"(a[2]), "r"(a[3]), "r"(b0), "r"(b1));
}
__device__ __forceinline__ void cpa16(uint32_t saddr, const void* gptr) {
    asm volatile("cp.async.cg.shared.global [%0], [%1], 16;"
                 :: "r"(saddr), "l"(gptr) : "memory");
}
__device__ __forceinline__ uint32_t packbf2(float a, float b) {
    __nv_bfloat162 p = __halves2bfloat162(__float2bfloat16(a), __float2bfloat16(b));
    return *reinterpret_cast<uint32_t*>(&p);
}
__device__ __forceinline__ void acch(float4& acc, uint2 u, float wgt) {
    float2 a = __half22float2(*reinterpret_cast<__half2*>(&u.x));
    float2 b = __half22float2(*reinterpret_cast<__half2*>(&u.y));
    acc.x = fmaf(wgt, a.x, acc.x);
    acc.y = fmaf(wgt, a.y, acc.y);
    acc.z = fmaf(wgt, b.x, acc.z);
    acc.w = fmaf(wgt, b.y, acc.w);
}

// ------------------------- side-stream head: zero counters/degrees -------------------------
__global__ void zero_kernel() {
    int i = blockIdx.x * blockDim.x + threadIdx.x;
    if (i < NN) { g_deg[i] = 0.f; g_cnt[i] = 0; }
}

// ------------------------- fused: stat zero + weight split + embedding gather -------------------------
#define WCNT (9 * 16384)
__global__ void fused0_kernel(const int* __restrict__ xidx, const float* __restrict__ emb,
                              const float* __restrict__ Wt, const float* __restrict__ Wc) {
    int i = blockIdx.x * blockDim.x + threadIdx.x;
    if (i < 5 * 256) ((float*)g_stat)[i] = 0.f;
    int j = i;
    if (j < WCNT) {
        int m = j >> 14, r = j & 16383, n = r >> 7, k = r & 127;
        float f;
        if (m < 3) f = Wt[m * 16384 + k * 128 + n];
        else { int mm = m - 3, ii = mm >> 1, op = mm & 1; f = Wc[ii * 32768 + (op * 128 + k) * 128 + n]; }
        __nv_bfloat16 h = __float2bfloat16(f);
        g_Bhi[j] = h;
        g_Blo[j] = __float2bfloat16(f - __bfloat162float(h));
    }
    int g = i - WCNT;
    if (g >= 0 && g < NN * 32) {
        int node = g >> 5;
        int c4 = (g & 31) << 2;
        int a = xidx[node];
        *(float4*)(g_B0 + (size_t)node * HD + c4) = *(const float4*)(emb + (size_t)a * HD + c4);
    }
}

// ------------------------- graph preprocessing -------------------------
__global__ void hist_kernel(const int* __restrict__ erow, const float* __restrict__ ew) {
    int i = blockIdx.x * blockDim.x + threadIdx.x;
    if (i < NE) {
        int r = erow[i];
        atomicAdd(&g_deg[r], ew[i]);
        atomicAdd(&g_cnt[r], 1);
    }
}

__global__ void scan1_kernel() {
    __shared__ int sh[1024];
    int t = threadIdx.x;
    int i = blockIdx.x * 1024 + t;
    int v = (i < NN) ? g_cnt[i] : 0;
    sh[t] = v;
    __syncthreads();
    for (int off = 1; off < 1024; off <<= 1) {
        int x = (t >= off) ? sh[t - off] : 0;
        __syncthreads();
        sh[t] += x;
        __syncthreads();
    }
    if (i < NN) g_rowptr[i] = sh[t] - v;
    if (t == 1023) g_part[blockIdx.x] = sh[1023];
}

__global__ void scan2_kernel() {
    if (threadIdx.x == 0) {
        int run = 0;
        for (int b = 0; b < NSCANB; b++) { int v = g_part[b]; g_part[b] = run; run += v; }
    }
}

// scan finalize + inv-degree (fused)
__global__ void scan3_kernel() {
    int i = blockIdx.x * blockDim.x + threadIdx.x;
    if (i < NN) {
        int v = g_rowptr[i] + g_part[i >> 10];
        g_rowptr[i] = v;
        g_cursor[i] = v;
        float d = g_deg[i];
        d = (d < 0.5f) ? d + 1.f : d;
        g_deg[i] = 1.f / d;
    }
    if (i == 0) g_rowptr[NN] = NE;
}

__global__ void scatter_kernel(const int* __restrict__ erow, const int* __restrict__ ecol,
                               const float* __restrict__ ew) {
    int i = blockIdx.x * blockDim.x + threadIdx.x;
    if (i < NE) {
        int r = erow[i];
        int p = atomicAdd(&g_cursor[r], 1);
        g_ec[p] = ecol[i];
        g_ewn[p] = ew[i] * g_deg[r];
    }
}

// ------------------------- SpMM: warp per row, 64 rows/block, 16-wide MLP, fused stats -------------------------
#define SPB2 1563   // ceil(NN/64)
__global__ void spmm_kernel(const __half* __restrict__ Hh, float* __restrict__ Mo,
                            float* __restrict__ stat) {
    __shared__ float sred[256];
    int tid = threadIdx.x, lane = tid & 31, wid = tid >> 5;
    sred[tid] = 0.f;
    __syncthreads();
    int c4 = lane * 4;
    int base = blockIdx.x * 64;
    float4 lsum = make_float4(0.f, 0.f, 0.f, 0.f);
    float4 lsq  = make_float4(0.f, 0.f, 0.f, 0.f);

    for (int it = 0; it < 8; it++) {
        int gw = base + it * 8 + wid;
        if (gw >= NN) break;
        int s = g_rowptr[gw], e = g_rowptr[gw + 1];
        float4 acc = make_float4(0.f, 0.f, 0.f, 0.f);

        int i = s;
        int pre = (s + 3) & ~3;
        if (pre > e) pre = e;
        for (; i < pre; i++) {
            uint2 u = *(const uint2*)(Hh + (size_t)g_ec[i] * HD + c4);
            acch(acc, u, g_ewn[i]);
        }
        // 16-edge unrolled main loop: 16 independent gathers in flight
        for (; i + 16 <= e; i += 16) {
            int4   ia = *(const int4*)(g_ec + i);
            int4   ib = *(const int4*)(g_ec + i + 4);
            int4   ic = *(const int4*)(g_ec + i + 8);
            int4   id = *(const int4*)(g_ec + i + 12);
            float4 wa = *(const float4*)(g_ewn + i);
            float4 wb = *(const float4*)(g_ewn + i + 4);
            float4 wc = *(const float4*)(g_ewn + i + 8);
            float4 wd = *(const float4*)(g_ewn + i + 12);
            uint2 u0 = *(const uint2*)(Hh + (size_t)ia.x * HD + c4);
            uint2 u1 = *(const uint2*)(Hh + (size_t)ia.y * HD + c4);
            uint2 u2 = *(const uint2*)(Hh + (size_t)ia.z * HD + c4);
            uint2 u3 = *(const uint2*)(Hh + (size_t)ia.w * HD + c4);
            uint2 u4 = *(const uint2*)(Hh + (size_t)ib.x * HD + c4);
            uint2 u5 = *(const uint2*)(Hh + (size_t)ib.y * HD + c4);
            uint2 u6 = *(const uint2*)(Hh + (size_t)ib.z * HD + c4);
            uint2 u7 = *(const uint2*)(Hh + (size_t)ib.w * HD + c4);
            uint2 u8 = *(const uint2*)(Hh + (size_t)ic.x * HD + c4);
            uint2 u9 = *(const uint2*)(Hh + (size_t)ic.y * HD + c4);
            uint2 uA = *(const uint2*)(Hh + (size_t)ic.z * HD + c4);
            uint2 uB = *(const uint2*)(Hh + (size_t)ic.w * HD + c4);
            uint2 uC = *(const uint2*)(Hh + (size_t)id.x * HD + c4);
            uint2 uD = *(const uint2*)(Hh + (size_t)id.y * HD + c4);
            uint2 uE = *(const uint2*)(Hh + (size_t)id.z * HD + c4);
            uint2 uF = *(const uint2*)(Hh + (size_t)id.w * HD + c4);
            acch(acc, u0, wa.x); acch(acc, u1, wa.y);
            acch(acc, u2, wa.z); acch(acc, u3, wa.w);
            acch(acc, u4, wb.x); acch(acc, u5, wb.y);
            acch(acc, u6, wb.z); acch(acc, u7, wb.w);
            acch(acc, u8, wc.x); acch(acc, u9, wc.y);
            acch(acc, uA, wc.z); acch(acc, uB, wc.w);
            acch(acc, uC, wd.x); acch(acc, uD, wd.y);
            acch(acc, uE, wd.z); acch(acc, uF, wd.w);
        }
        for (; i + 8 <= e; i += 8) {
            int4   ia = *(const int4*)(g_ec + i);
            int4   ib = *(const int4*)(g_ec + i + 4);
            float4 wa = *(const float4*)(g_ewn + i);
            float4 wb = *(const float4*)(g_ewn + i + 4);
            uint2 u0 = *(const uint2*)(Hh + (size_t)ia.x * HD + c4);
            uint2 u1 = *(const uint2*)(Hh + (size_t)ia.y * HD + c4);
            uint2 u2 = *(const uint2*)(Hh + (size_t)ia.z * HD + c4);
            uint2 u3 = *(const uint2*)(Hh + (size_t)ia.w * HD + c4);
            uint2 u4 = *(const uint2*)(Hh + (size_t)ib.x * HD + c4);
            uint2 u5 = *(const uint2*)(Hh + (size_t)ib.y * HD + c4);
            uint2 u6 = *(const uint2*)(Hh + (size_t)ib.z * HD + c4);
            uint2 u7 = *(const uint2*)(Hh + (size_t)ib.w * HD + c4);
            acch(acc, u0, wa.x); acch(acc, u1, wa.y);
            acch(acc, u2, wa.z); acch(acc, u3, wa.w);
            acch(acc, u4, wb.x); acch(acc, u5, wb.y);
            acch(acc, u6, wb.z); acch(acc, u7, wb.w);
        }
        for (; i < e; i++) {
            uint2 u = *(const uint2*)(Hh + (size_t)g_ec[i] * HD + c4);
            acch(acc, u, g_ewn[i]);
        }
        *(float4*)(Mo + (size_t)gw * HD + c4) = acc;
        lsum.x += acc.x; lsum.y += acc.y; lsum.z += acc.z; lsum.w += acc.w;
        lsq.x = fmaf(acc.x, acc.x, lsq.x);
        lsq.y = fmaf(acc.y, acc.y, lsq.y);
        lsq.z = fmaf(acc.z, acc.z, lsq.z);
        lsq.w = fmaf(acc.w, acc.w, lsq.w);
    }
    atomicAdd(&sred[c4 + 0], lsum.x); atomicAdd(&sred[c4 + 1], lsum.y);
    atomicAdd(&sred[c4 + 2], lsum.z); atomicAdd(&sred[c4 + 3], lsum.w);
    atomicAdd(&sred[128 + c4 + 0], lsq.x); atomicAdd(&sred[128 + c4 + 1], lsq.y);
    atomicAdd(&sred[128 + c4 + 2], lsq.z); atomicAdd(&sred[128 + c4 + 3], lsq.w);
    __syncthreads();
    atomicAdd(&stat[tid], sred[tid]);
}

// ------------------------- tensor-core GEMM (split bf16, mma.sync + ldmatrix) -------------------------
// 64-row tile, 256 threads (8 warps, 2x4 warpgrid, 32x32 warp tile), 2 CTAs/SM
// GraphNorm affine computed INLINE from raw stats; B staged via cp.async (overlapped
// with A transform); optional fused column stats on output (statout != 0).
// C[64-row tile, 128] = sum_op transform(Aop) @ Wop + bias
// transform: 0 = raw, 1 = affine(x*s+t), 2 = affine + relu (fused into fp32->bf16 split)
// D = Ahi*Bhi + Alo*Bhi + Ahi*Blo (3-term split; lo*lo ~2^-18 dropped)
#define GP 272                     // padded smem row pitch: 17x16B -> LDSM conflict-free
#define A_HI_OFF 0
#define A_LO_OFF 17408
#define B_HI_OFF 34816
#define B_LO_OFF 69632
#define AFF_OFF  104448            // affine: [op*256 + 0:128) scale, [op*256 + 128:256) shift
#define STAT_OFF 106496            // 256-float block stat buffer
#define GSMEM    107520

__global__ __launch_bounds__(256, 2) void gemm_mma(
    const float* __restrict__ A0, const float* __restrict__ ga0, const float* __restrict__ be0,
    const float* __restrict__ al0, const float* __restrict__ st0, int mode0,
    const float* __restrict__ A1, const float* __restrict__ ga1, const float* __restrict__ be1,
    const float* __restrict__ al1, const float* __restrict__ st1, int mode1,
    int nops, int bm0, int bm1,
    const float* __restrict__ bias, float* __restrict__ C, __half* __restrict__ Ch,
    int epi_relu, float* __restrict__ statout)
{
    extern __shared__ __align__(16) char smem[];
    uint32_t sb = smem_u32(smem);
    const int tid = threadIdx.x, lane = tid & 31, wid = tid >> 5;
    const int warp_m = wid >> 2, warp_n = wid & 3;   // 2 x 4 warp grid
    const int row0 = blockIdx.x * 64;
    float* aff = (float*)(smem + AFF_OFF);

    // ---- inline GraphNorm affine: scale/shift from raw column stats ----
    {
        int half = tid >> 7, c = tid & 127;
        int mode = half ? mode1 : mode0;
        if (half < nops && mode) {
            const float* ga = half ? ga1 : ga0;
            const float* be = half ? be1 : be0;
            const float* al = half ? al1 : al0;
            const float* st = half ? st1 : st0;
            float invn = 1.0f / (float)NN;
            float mean = st[c] * invn, e2 = st[128 + c] * invn;
            float a = al[c];
            float var = e2 - mean * mean * a * (2.0f - a);
            float rs = rsqrtf(var + EPSV);
            float g = ga[c];
            aff[half * 256 + c] = g * rs;
            aff[half * 256 + 128 + c] = be[c] - g * rs * a * mean;
        }
    }
    __syncthreads();

    float acc[2][4][4];
#pragma unroll
    for (int mt = 0; mt < 2; mt++)
#pragma unroll
        for (int nt = 0; nt < 4; nt++)
#pragma unroll
            for (int j = 0; j < 4; j++) acc[mt][nt][j] = 0.f;

    const int arow = tid >> 2;           // A staging row 0..63
    const int kq = (tid & 3) * 32;       // A staging k quarter
    const int grow = row0 + arow;

    // ldmatrix per-lane base addresses
    const uint32_t a_lm = sb + A_HI_OFF +
        (uint32_t)(warp_m * 32 + ((lane >> 3) & 1) * 8 + (lane & 7)) * GP +
        (uint32_t)((lane >> 4) & 1) * 16;
    const uint32_t b_lm = sb + B_HI_OFF +
        (uint32_t)(warp_n * 32 + ((lane >> 4) & 1) * 8 + (lane & 7)) * GP +
        (uint32_t)((lane >> 3) & 1) * 16;

    for (int op = 0; op < nops; op++) {
        const float* A = op ? A1 : A0;
        const float* ss = aff + op * 256;
        const float* tt = ss + 128;
        const int mode = op ? mode1 : mode0;
        const int bm = op ? bm1 : bm0;

        if (op > 0) __syncthreads();   // previous op's frags fully consumed

        // ---- stage B hi/lo via cp.async (overlaps with A transform below) ----
        {
            const char* Bh = (const char*)(g_Bhi + (size_t)bm * 16384);
            const char* Bl = (const char*)(g_Blo + (size_t)bm * 16384);
            uint32_t kb = (uint32_t)(tid & 15) * 16;         // byte offset within row
            int rbase = tid >> 4;                             // 0..15
#pragma unroll
            for (int it = 0; it < 8; it++) {
                int goff = (it * 256 + tid) * 16;             // global byte offset
                int rowb = it * 16 + rbase;
                uint32_t soff = (uint32_t)rowb * GP + kb;
                cpa16(sb + B_HI_OFF + soff, Bh + goff);
                cpa16(sb + B_LO_OFF + soff, Bl + goff);
            }
            asm volatile("cp.async.commit_group;" ::: "memory");
        }

        // ---- stage A hi/lo (fused transform + split) ----
#pragma unroll
        for (int c = 0; c < 4; c++) {
            int k0 = kq + c * 8;
            float f[8];
            if (grow < NN) {
                float4 a = *(const float4*)(A + (size_t)grow * HD + k0);
                float4 b = *(const float4*)(A + (size_t)grow * HD + k0 + 4);
                f[0] = a.x; f[1] = a.y; f[2] = a.z; f[3] = a.w;
                f[4] = b.x; f[5] = b.y; f[6] = b.z; f[7] = b.w;
            } else {
#pragma unroll
                for (int j = 0; j < 8; j++) f[j] = 0.f;
            }
            if (mode) {
                float4 sv0 = *(const float4*)(ss + k0);
                float4 sv1 = *(const float4*)(ss + k0 + 4);
                float4 tv0 = *(const float4*)(tt + k0);
                float4 tv1 = *(const float4*)(tt + k0 + 4);
                f[0] = fmaf(f[0], sv0.x, tv0.x); f[1] = fmaf(f[1], sv0.y, tv0.y);
                f[2] = fmaf(f[2], sv0.z, tv0.z); f[3] = fmaf(f[3], sv0.w, tv0.w);
                f[4] = fmaf(f[4], sv1.x, tv1.x); f[5] = fmaf(f[5], sv1.y, tv1.y);
                f[6] = fmaf(f[6], sv1.z, tv1.z); f[7] = fmaf(f[7], sv1.w, tv1.w);
                if (mode == 2) {
#pragma unroll
                    for (int j = 0; j < 8; j++) f[j] = fmaxf(f[j], 0.f);
                }
            }
            float hi[8], lo[8];
#pragma unroll
            for (int j = 0; j < 8; j++) {
                hi[j] = __bfloat162float(__float2bfloat16(f[j]));
                lo[j] = f[j] - hi[j];
            }
            uint32_t off = (uint32_t)arow * GP + (uint32_t)k0 * 2;
            *(uint4*)(smem + A_HI_OFF + off) =
                make_uint4(packbf2(hi[0], hi[1]), packbf2(hi[2], hi[3]),
                           packbf2(hi[4], hi[5]), packbf2(hi[6], hi[7]));
            *(uint4*)(smem + A_LO_OFF + off) =
                make_uint4(packbf2(lo[0], lo[1]), packbf2(lo[2], lo[3]),
                           packbf2(lo[4], lo[5]), packbf2(lo[6], lo[7]));
        }
        asm volatile("cp.async.wait_group 0;" ::: "memory");
        __syncthreads();

        // ---- compute: per k-step, LDSM fragments + 3-term split MMAs ----
#pragma unroll 2
        for (int ks = 0; ks < 8; ks++) {
            const uint32_t k2 = (uint32_t)ks * 32;           // byte offset of k-step
            uint32_t bh[2][4], bl[2][4];
#pragma unroll
            for (int ntp = 0; ntp < 2; ntp++) {
                uint32_t ba = b_lm + (uint32_t)(ntp * 16) * GP + k2;
                ldsm4(bh[ntp], ba);
                ldsm4(bl[ntp], ba + (B_LO_OFF - B_HI_OFF));
            }
            uint32_t ah[2][4], al[2][4];
#pragma unroll
            for (int mt = 0; mt < 2; mt++) {
                uint32_t aa = a_lm + (uint32_t)(mt * 16) * GP + k2;
                ldsm4(ah[mt], aa);
                ldsm4(al[mt], aa + (A_LO_OFF - A_HI_OFF));
            }
            // term 1: Ahi x Bhi (8 independent acc targets)
#pragma unroll
            for (int mt = 0; mt < 2; mt++)
#pragma unroll
                for (int ntp = 0; ntp < 2; ntp++) {
                    mma16816(acc[mt][2 * ntp],     ah[mt], bh[ntp][0], bh[ntp][1]);
                    mma16816(acc[mt][2 * ntp + 1], ah[mt], bh[ntp][2], bh[ntp][3]);
                }
            // term 2: Alo x Bhi
#pragma unroll
            for (int mt = 0; mt < 2; mt++)
#pragma unroll
                for (int ntp = 0; ntp < 2; ntp++) {
                    mma16816(acc[mt][2 * ntp],     al[mt], bh[ntp][0], bh[ntp][1]);
                    mma16816(acc[mt][2 * ntp + 1], al[mt], bh[ntp][2], bh[ntp][3]);
                }
            // term 3: Ahi x Blo
#pragma unroll
            for (int mt = 0; mt < 2; mt++)
#pragma unroll
                for (int ntp = 0; ntp < 2; ntp++) {
                    mma16816(acc[mt][2 * ntp],     ah[mt], bl[ntp][0], bl[ntp][1]);
                    mma16816(acc[mt][2 * ntp + 1], ah[mt], bl[ntp][2], bl[ntp][3]);
                }
        }
    }

    // ---- epilogue: bias, optional relu, store (fp32 or fp16), optional fused stats ----
    float csum[4][2], csq[4][2];
#pragma unroll
    for (int nt = 0; nt < 4; nt++) {
        csum[nt][0] = csum[nt][1] = 0.f;
        csq[nt][0] = csq[nt][1] = 0.f;
    }
#pragma unroll
    for (int mt = 0; mt < 2; mt++) {
        int r0 = row0 + warp_m * 32 + mt * 16 + (lane >> 2);
#pragma unroll
        for (int nt = 0; nt < 4; nt++) {
            int cidx = warp_n * 32 + nt * 8 + (lane & 3) * 2;
            float bx = bias[cidx], by = bias[cidx + 1];
            float v0 = acc[mt][nt][0] + bx, v1 = acc[mt][nt][1] + by;
            float v2 = acc[mt][nt][2] + bx, v3 = acc[mt][nt][3] + by;
            if (epi_relu) {
                v0 = fmaxf(v0, 0.f); v1 = fmaxf(v1, 0.f);
                v2 = fmaxf(v2, 0.f); v3 = fmaxf(v3, 0.f);
            }
            if (statout) {
                if (r0 < NN) {
                    csum[nt][0] += v0; csq[nt][0] = fmaf(v0, v0, csq[nt][0]);
                    csum[nt][1] += v1; csq[nt][1] = fmaf(v1, v1, csq[nt][1]);
                }
                if (r0 + 8 < NN) {
                    csum[nt][0] += v2; csq[nt][0] = fmaf(v2, v2, csq[nt][0]);
                    csum[nt][1] += v3; csq[nt][1] = fmaf(v3, v3, csq[nt][1]);
                }
            }
            if (Ch) {
                if (r0 < NN)
                    *(__half2*)(Ch + (size_t)r0 * HD + cidx) = __floats2half2_rn(v0, v1);
                if (r0 + 8 < NN)
                    *(__half2*)(Ch + (size_t)(r0 + 8) * HD + cidx) = __floats2half2_rn(v2, v3);
            } else {
                if (r0 < NN)
                    *(float2*)(C + (size_t)r0 * HD + cidx) = make_float2(v0, v1);
                if (r0 + 8 < NN)
                    *(float2*)(C + (size_t)(r0 + 8) * HD + cidx) = make_float2(v2, v3);
            }
        }
    }
    if (statout) {
        float* sstat = (float*)(smem + STAT_OFF);
        sstat[tid] = 0.f;
        __syncthreads();
#pragma unroll
        for (int nt = 0; nt < 4; nt++) {
#pragma unroll
            for (int j = 0; j < 2; j++) {
                float s = csum[nt][j], q = csq[nt][j];
                s += __shfl_down_sync(0xffffffffu, s, 16);
                s += __shfl_down_sync(0xffffffffu, s, 8);
                s += __shfl_down_sync(0xffffffffu, s, 4);
                q += __shfl_down_sync(0xffffffffu, q, 16);
                q += __shfl_down_sync(0xffffffffu, q, 8);
                q += __shfl_down_sync(0xffffffffu, q, 4);
                if ((lane >> 2) == 0) {
                    int cidx = warp_n * 32 + nt * 8 + (lane & 3) * 2 + j;
                    atomicAdd(&sstat[cidx], s);
                    atomicAdd(&sstat[128 + cidx], q);
                }
            }
        }
        __syncthreads();
        atomicAdd(&statout[tid], sstat[tid]);
    }
}

// ------------------------- launch -------------------------
extern "C" void kernel_launch(void* const* d_in, const int* in_sizes, int n_in,
                              void* d_out, int out_size) {
    const int*   x_idx = (const int*)d_in[0];
    const int*   erow  = (const int*)d_in[1];
    const int*   ecol  = erow + NE;
    const float* ew    = (const float*)d_in[2];
    const float* emb   = (const float*)d_in[3];
    const float* Wt    = (const float*)d_in[4];
    const float* bt    = (const float*)d_in[5];
    const float* Wc    = (const float*)d_in[6];
    const float* bc    = (const float*)d_in[7];
    const float* cg_g  = (const float*)d_in[8];
    const float* cg_b  = (const float*)d_in[9];
    const float* cg_a  = (const float*)d_in[10];
    const float* gn_g  = (const float*)d_in[11];
    const float* gn_b  = (const float*)d_in[12];
    const float* gn_a  = (const float*)d_in[13];

    void* p;
    cudaGetSymbolAddress(&p, g_B0);   float*  B0 = (float*)p;
    cudaGetSymbolAddress(&p, g_B1);   float*  B1 = (float*)p;
    cudaGetSymbolAddress(&p, g_Hh);   __half* Hb = (__half*)p;
    cudaGetSymbolAddress(&p, g_M);    float*  Mb = (float*)p;
    cudaGetSymbolAddress(&p, g_stat); float*  ST = (float*)p;   // [5][256]

    cudaFuncSetAttribute(gemm_mma, cudaFuncAttributeMaxDynamicSharedMemorySize, GSMEM);

    const int TB = 256;
    const int GB = (NN + 63) / 64;     // 1563 GEMM tiles
    const int F0B = (WCNT + NN * 32 + TB - 1) / TB;
    const float* FN = (const float*)0;
    float* FNo = (float*)0;

    // side stream: CSR preprocessing runs fully parallel with fused0 + gemm1-L0
    cudaStream_t s2;
    cudaStreamCreateWithFlags(&s2, cudaStreamNonBlocking);
    cudaEvent_t ev0, ev1;
    cudaEventCreateWithFlags(&ev0, cudaEventDisableTiming);
    cudaEventCreateWithFlags(&ev1, cudaEventDisableTiming);

    // main: fused0 -> gemm1(L0) -------------------------wait(ev1)-> spmm ...
    // side: zero -> hist -> scan1 -> scan2 -> scan3 -> scatter -----/
    cudaEventRecord(ev0, 0);               // graph root marker
    cudaStreamWaitEvent(s2, ev0, 0);
    zero_kernel<<<(NN + TB - 1) / TB, TB, 0, s2>>>();
    hist_kernel<<<(NE + TB - 1) / TB, TB, 0, s2>>>(erow, ew);
    fused0_kernel<<<F0B, TB>>>(x_idx, emb, Wt, Wc);
    scan1_kernel<<<NSCANB, 1024, 0, s2>>>();
    // gemm_mma (profiled): h = relu(x @ Wt[0] + bt[0]) -> fp16
    gemm_mma<<<GB, TB, GSMEM>>>(B0, FN, FN, FN, FN, 0,
                                FN, FN, FN, FN, FN, 0,
                                1, 0, 0, bt, (float*)0, Hb, 1, FNo);
    scan2_kernel<<<1, 32, 0, s2>>>();
    scan3_kernel<<<(NN + TB - 1) / TB, TB, 0, s2>>>();
    scatter_kernel<<<(NE + TB - 1) / TB, TB, 0, s2>>>(erow, ecol, ew);
    cudaEventRecord(ev1, s2);
    cudaStreamWaitEvent(0, ev1, 0);

    const float* Xcur = B0;
    int modeX = 0;
    for (int i = 0; i < 3; i++) {
        const float* gnst = (i > 0) ? (ST + (3 + i - 1) * 256) : FN;
        const float* gng = (i > 0) ? gn_g + (i - 1) * HD : FN;
        const float* gnb = (i > 0) ? gn_b + (i - 1) * HD : FN;
        const float* gna = (i > 0) ? gn_a + (i - 1) * HD : FN;
        if (i > 0) {
            // h = relu(gn_affine(x) @ Wt[i] + bt[i]) -> fp16
            gemm_mma<<<GB, TB, GSMEM>>>(Xcur, gng, gnb, gna, gnst, modeX,
                                        FN, FN, FN, FN, FN, 0,
                                        1, i, 0, bt + i * HD, (float*)0, Hb, 1, FNo);
        }
        // m = A_mean @ h (CSR, no atomics) + fused cg column stats
        spmm_kernel<<<SPB2, TB>>>(Hb, Mb, ST + i * 256);
        // out = cg_affine(m) @ Wc[i][:128] + gn_affine(x) @ Wc[i][128:] + bc[i]
        //       (+ fused gn column stats on out for i<2)
        float* Onext = (i == 2) ? (float*)d_out : ((i == 0) ? B1 : B0);
        float* statout = (i < 2) ? (ST + (3 + i) * 256) : FNo;
        gemm_mma<<<GB, TB, GSMEM>>>(Mb, cg_g + i * HD, cg_b + i * HD, cg_a + i * HD,
                                    ST + i * 256, 1,
                                    Xcur, gng, gnb, gna, gnst, modeX,
                                    2, 3 + i * 2, 3 + i * 2 + 1, bc + i * HD,
                                    Onext, (__half*)0, 0, statout);
        if (i < 2) {
            Xcur = Onext;
            modeX = 2;
        }
    }

    cudaEventDestroy(ev0);
    cudaEventDestroy(ev1);
    cudaStreamDestroy(s2);
}

// round 17
// speedup vs baseline: 1.0106x; 1.0106x over previous
#include <cuda_runtime.h>
#include <cuda_fp16.h>
#include <cuda_bf16.h>
#include <cstdint>

#define NN 100000
#define NE 3200000
#define HD 128
#define EPSV 1e-5f
#define NSCANB 98   // ceil(NN/1024)

// ------------------------- device scratch (no allocs allowed) -------------------------
__device__ float  g_B0[NN * HD];      // x / layer output ping
__device__ float  g_B1[NN * HD];      // layer output pong
__device__ __half g_Hh[NN * HD];      // h = relu(x@Wt+bt) in fp16 (SpMM operand)
__device__ float  g_M[NN * HD];       // aggregated messages
__device__ int    g_rowptr[NN + 1];
__device__ int    g_cursor[NN];
__device__ int    g_cnt[NN];
__device__ int    g_ec[NE];           // CSR column indices
__device__ float  g_ewn[NE];          // CSR edge weights (raw, CSR order)
__device__ int    g_part[128];        // scan partials
// column stats: [0:128) sum, [128:256) sumsq. [0..2]=cg layer i, [3..4]=gn layer i
__device__ float  g_stat[5][256];
// split-bf16 weights, [n][k] layout: 9 matrices (Wt x3, then (Wc[i] op-half) x6)
__device__ __nv_bfloat16 g_Bhi[9 * 16384];
__device__ __nv_bfloat16 g_Blo[9 * 16384];

// ------------------------- helpers -------------------------
__device__ __forceinline__ uint32_t smem_u32(const void* p) {
    uint32_t a;
    asm("{ .reg .u64 t; cvta.to.shared.u64 t, %1; cvt.u32.u64 %0, t; }" : "=r"(a) : "l"(p));
    return a;
}
__device__ __forceinline__ void ldsm4(uint32_t* r, uint32_t addr) {
    asm volatile("ldmatrix.sync.aligned.m8n8.x4.shared.b16 {%0,%1,%2,%3}, [%4];"
                 : "=r"(r[0]), "=r"(r[1]), "=r"(r[2]), "=r"(r[3]) : "r"(addr));
}
__device__ __forceinline__ void mma16816(float* c, const uint32_t* a, uint32_t b0,
                                         uint32_t b1) {
    asm volatile(
        "mma.sync.aligned.m16n8k16.row.col.f32.bf16.bf16.f32 "
        "{%0,%1,%2,%3}, {%4,%5,%6,%7}, {%8,%9}, {%0,%1,%2,%3};"
        : "+f"(c[0]), "+f"(c[1]), "+f"(c[2]), "+f"(c[3])
        : "r"(a[0]), "r"(a[1]), "r"(a[2]), "r"(a[3]), "r"(b0), "r"(b1));
}
__device__ __forceinline__ void cpa16(uint32_t saddr, const void* gptr) {
    asm volatile("cp.async.cg.shared.global [%0], [%1], 16;"
                 :: "r"(saddr), "l"(gptr) : "memory");
}
__device__ __forceinline__ uint32_t packbf2(float a, float b) {
    __nv_bfloat162 p = __halves2bfloat162(__float2bfloat16(a), __float2bfloat16(b));
    return *reinterpret_cast<uint32_t*>(&p);
}
__device__ __forceinline__ void acch(float4& acc, uint2 u, float wgt) {
    float2 a = __half22float2(*reinterpret_cast<__half2*>(&u.x));
    float2 b = __half22float2(*reinterpret_cast<__half2*>(&u.y));
    acc.x = fmaf(wgt, a.x, acc.x);
    acc.y = fmaf(wgt, a.y, acc.y);
    acc.z = fmaf(wgt, b.x, acc.z);
    acc.w = fmaf(wgt, b.y, acc.w);
}

// ------------------------- fused: zero + stat zero + weight split + embedding gather -------------------------
#define WCNT (9 * 16384)
__global__ void fused0_kernel(const int* __restrict__ xidx, const float* __restrict__ emb,
                              const float* __restrict__ Wt, const float* __restrict__ Wc) {
    int i = blockIdx.x * blockDim.x + threadIdx.x;
    if (i < NN) g_cnt[i] = 0;
    if (i < 5 * 256) ((float*)g_stat)[i] = 0.f;
    int j = i - NN;
    if (j >= 0 && j < WCNT) {
        int m = j >> 14, r = j & 16383, n = r >> 7, k = r & 127;
        float f;
        if (m < 3) f = Wt[m * 16384 + k * 128 + n];
        else { int mm = m - 3, ii = mm >> 1, op = mm & 1; f = Wc[ii * 32768 + (op * 128 + k) * 128 + n]; }
        __nv_bfloat16 h = __float2bfloat16(f);
        g_Bhi[j] = h;
        g_Blo[j] = __float2bfloat16(f - __bfloat162float(h));
    }
    int g = i - NN - WCNT;
    if (g >= 0 && g < NN * 32) {
        int node = g >> 5;
        int c4 = (g & 31) << 2;
        int a = xidx[node];
        *(float4*)(g_B0 + (size_t)node * HD + c4) = *(const float4*)(emb + (size_t)a * HD + c4);
    }
}

// ------------------------- graph preprocessing -------------------------
__global__ void hist_kernel(const int* __restrict__ erow) {
    int i = blockIdx.x * blockDim.x + threadIdx.x;
    if (i < NE) atomicAdd(&g_cnt[erow[i]], 1);
}

__global__ void scan1_kernel() {
    __shared__ int sh[1024];
    int t = threadIdx.x;
    int i = blockIdx.x * 1024 + t;
    int v = (i < NN) ? g_cnt[i] : 0;
    sh[t] = v;
    __syncthreads();
    for (int off = 1; off < 1024; off <<= 1) {
        int x = (t >= off) ? sh[t - off] : 0;
        __syncthreads();
        sh[t] += x;
        __syncthreads();
    }
    if (i < NN) g_rowptr[i] = sh[t] - v;
    if (t == 1023) g_part[blockIdx.x] = sh[1023];
}

// scan finalize with inline cross-block prefix (scan2 folded in)
__global__ void scan3_kernel() {
    __shared__ int pref[NSCANB];
    int t = threadIdx.x;
    if (t < NSCANB) pref[t] = g_part[t];
    __syncthreads();
    if (t == 0) {
        int run = 0;
        for (int b = 0; b < NSCANB; b++) { int v = pref[b]; pref[b] = run; run += v; }
    }
    __syncthreads();
    int i = blockIdx.x * blockDim.x + t;
    if (i < NN) {
        int v = g_rowptr[i] + pref[i >> 10];
        g_rowptr[i] = v;
        g_cursor[i] = v;
    }
    if (i == 0) g_rowptr[NN] = NE;
}

__global__ void scatter_kernel(const int* __restrict__ erow, const int* __restrict__ ecol,
                               const float* __restrict__ ew) {
    int i = blockIdx.x * blockDim.x + threadIdx.x;
    if (i < NE) {
        int r = erow[i];
        int p = atomicAdd(&g_cursor[r], 1);
        g_ec[p] = ecol[i];
        g_ewn[p] = ew[i];
    }
}

// ------------------------- SpMM: warp/row, 16-wide MLP, inline mean-norm, fused stats -------------------------
#define SPB2 1563   // ceil(NN/64)
__global__ void spmm_kernel(const __half* __restrict__ Hh, float* __restrict__ Mo,
                            float* __restrict__ stat) {
    __shared__ float sred[256];
    int tid = threadIdx.x, lane = tid & 31, wid = tid >> 5;
    sred[tid] = 0.f;
    __syncthreads();
    int c4 = lane * 4;
    int base = blockIdx.x * 64;
    float4 lsum = make_float4(0.f, 0.f, 0.f, 0.f);
    float4 lsq  = make_float4(0.f, 0.f, 0.f, 0.f);

    for (int it = 0; it < 8; it++) {
        int gw = base + it * 8 + wid;
        if (gw >= NN) break;
        int s = g_rowptr[gw], e = g_rowptr[gw + 1];
        float4 acc = make_float4(0.f, 0.f, 0.f, 0.f);
        float wsum = 0.f;

        int i = s;
        int pre = (s + 3) & ~3;
        if (pre > e) pre = e;
        for (; i < pre; i++) {
            float w = g_ewn[i];
            uint2 u = *(const uint2*)(Hh + (size_t)g_ec[i] * HD + c4);
            acch(acc, u, w);
            wsum += w;
        }
        // 16-edge unrolled main loop: 16 independent gathers in flight
        for (; i + 16 <= e; i += 16) {
            int4   ia = *(const int4*)(g_ec + i);
            int4   ib = *(const int4*)(g_ec + i + 4);
            int4   ic = *(const int4*)(g_ec + i + 8);
            int4   id = *(const int4*)(g_ec + i + 12);
            float4 wa = *(const float4*)(g_ewn + i);
            float4 wb = *(const float4*)(g_ewn + i + 4);
            float4 wc = *(const float4*)(g_ewn + i + 8);
            float4 wd = *(const float4*)(g_ewn + i + 12);
            uint2 u0 = *(const uint2*)(Hh + (size_t)ia.x * HD + c4);
            uint2 u1 = *(const uint2*)(Hh + (size_t)ia.y * HD + c4);
            uint2 u2 = *(const uint2*)(Hh + (size_t)ia.z * HD + c4);
            uint2 u3 = *(const uint2*)(Hh + (size_t)ia.w * HD + c4);
            uint2 u4 = *(const uint2*)(Hh + (size_t)ib.x * HD + c4);
            uint2 u5 = *(const uint2*)(Hh + (size_t)ib.y * HD + c4);
            uint2 u6 = *(const uint2*)(Hh + (size_t)ib.z * HD + c4);
            uint2 u7 = *(const uint2*)(Hh + (size_t)ib.w * HD + c4);
            uint2 u8 = *(const uint2*)(Hh + (size_t)ic.x * HD + c4);
            uint2 u9 = *(const uint2*)(Hh + (size_t)ic.y * HD + c4);
            uint2 uA = *(const uint2*)(Hh + (size_t)ic.z * HD + c4);
            uint2 uB = *(const uint2*)(Hh + (size_t)ic.w * HD + c4);
            uint2 uC = *(const uint2*)(Hh + (size_t)id.x * HD + c4);
            uint2 uD = *(const uint2*)(Hh + (size_t)id.y * HD + c4);
            uint2 uE = *(const uint2*)(Hh + (size_t)id.z * HD + c4);
            uint2 uF = *(const uint2*)(Hh + (size_t)id.w * HD + c4);
            acch(acc, u0, wa.x); acch(acc, u1, wa.y);
            acch(acc, u2, wa.z); acch(acc, u3, wa.w);
            acch(acc, u4, wb.x); acch(acc, u5, wb.y);
            acch(acc, u6, wb.z); acch(acc, u7, wb.w);
            acch(acc, u8, wc.x); acch(acc, u9, wc.y);
            acch(acc, uA, wc.z); acch(acc, uB, wc.w);
            acch(acc, uC, wd.x); acch(acc, uD, wd.y);
            acch(acc, uE, wd.z); acch(acc, uF, wd.w);
            wsum += wa.x + wa.y + wa.z + wa.w + wb.x + wb.y + wb.z + wb.w +
                    wc.x + wc.y + wc.z + wc.w + wd.x + wd.y + wd.z + wd.w;
        }
        for (; i + 8 <= e; i += 8) {
            int4   ia = *(const int4*)(g_ec + i);
            int4   ib = *(const int4*)(g_ec + i + 4);
            float4 wa = *(const float4*)(g_ewn + i);
            float4 wb = *(const float4*)(g_ewn + i + 4);
            uint2 u0 = *(const uint2*)(Hh + (size_t)ia.x * HD + c4);
            uint2 u1 = *(const uint2*)(Hh + (size_t)ia.y * HD + c4);
            uint2 u2 = *(const uint2*)(Hh + (size_t)ia.z * HD + c4);
            uint2 u3 = *(const uint2*)(Hh + (size_t)ia.w * HD + c4);
            uint2 u4 = *(const uint2*)(Hh + (size_t)ib.x * HD + c4);
            uint2 u5 = *(const uint2*)(Hh + (size_t)ib.y * HD + c4);
            uint2 u6 = *(const uint2*)(Hh + (size_t)ib.z * HD + c4);
            uint2 u7 = *(const uint2*)(Hh + (size_t)ib.w * HD + c4);
            acch(acc, u0, wa.x); acch(acc, u1, wa.y);
            acch(acc, u2, wa.z); acch(acc, u3, wa.w);
            acch(acc, u4, wb.x); acch(acc, u5, wb.y);
            acch(acc, u6, wb.z); acch(acc, u7, wb.w);
            wsum += wa.x + wa.y + wa.z + wa.w + wb.x + wb.y + wb.z + wb.w;
        }
        for (; i < e; i++) {
            float w = g_ewn[i];
            uint2 u = *(const uint2*)(Hh + (size_t)g_ec[i] * HD + c4);
            acch(acc, u, w);
            wsum += w;
        }
        // mean normalization: deg<0.5 -> deg+1
        float d = (wsum < 0.5f) ? wsum + 1.f : wsum;
        float inv = 1.f / d;
        acc.x *= inv; acc.y *= inv; acc.z *= inv; acc.w *= inv;
        *(float4*)(Mo + (size_t)gw * HD + c4) = acc;
        lsum.x += acc.x; lsum.y += acc.y; lsum.z += acc.z; lsum.w += acc.w;
        lsq.x = fmaf(acc.x, acc.x, lsq.x);
        lsq.y = fmaf(acc.y, acc.y, lsq.y);
        lsq.z = fmaf(acc.z, acc.z, lsq.z);
        lsq.w = fmaf(acc.w, acc.w, lsq.w);
    }
    atomicAdd(&sred[c4 + 0], lsum.x); atomicAdd(&sred[c4 + 1], lsum.y);
    atomicAdd(&sred[c4 + 2], lsum.z); atomicAdd(&sred[c4 + 3], lsum.w);
    atomicAdd(&sred[128 + c4 + 0], lsq.x); atomicAdd(&sred[128 + c4 + 1], lsq.y);
    atomicAdd(&sred[128 + c4 + 2], lsq.z); atomicAdd(&sred[128 + c4 + 3], lsq.w);
    __syncthreads();
    atomicAdd(&stat[tid], sred[tid]);
}

// ------------------------- tensor-core GEMM (split bf16, mma.sync + ldmatrix) -------------------------
// 64-row tile, 256 threads (8 warps, 2x4 warpgrid, 32x32 warp tile), 2 CTAs/SM
// GraphNorm affine computed INLINE from raw stats; B staged via cp.async (overlapped
// with A transform); optional fused column stats on output (statout != 0).
// C[64-row tile, 128] = sum_op transform(Aop) @ Wop + bias
// transform: 0 = raw, 1 = affine(x*s+t), 2 = affine + relu (fused into fp32->bf16 split)
// D = Ahi*Bhi + Alo*Bhi + Ahi*Blo (3-term split; lo*lo ~2^-18 dropped)
#define GP 272                     // padded smem row pitch: 17x16B -> LDSM conflict-free
#define A_HI_OFF 0
#define A_LO_OFF 17408
#define B_HI_OFF 34816
#define B_LO_OFF 69632
#define AFF_OFF  104448            // affine: [op*256 + 0:128) scale, [op*256 + 128:256) shift
#define STAT_OFF 106496            // 256-float block stat buffer
#define GSMEM    107520

__global__ __launch_bounds__(256, 2) void gemm_mma(
    const float* __restrict__ A0, const float* __restrict__ ga0, const float* __restrict__ be0,
    const float* __restrict__ al0, const float* __restrict__ st0, int mode0,
    const float* __restrict__ A1, const float* __restrict__ ga1, const float* __restrict__ be1,
    const float* __restrict__ al1, const float* __restrict__ st1, int mode1,
    int nops, int bm0, int bm1,
    const float* __restrict__ bias, float* __restrict__ C, __half* __restrict__ Ch,
    int epi_relu, float* __restrict__ statout)
{
    extern __shared__ __align__(16) char smem[];
    uint32_t sb = smem_u32(smem);
    const int tid = threadIdx.x, lane = tid & 31, wid = tid >> 5;
    const int warp_m = wid >> 2, warp_n = wid & 3;   // 2 x 4 warp grid
    const int row0 = blockIdx.x * 64;
    float* aff = (float*)(smem + AFF_OFF);

    // ---- inline GraphNorm affine: scale/shift from raw column stats ----
    {
        int half = tid >> 7, c = tid & 127;
        int mode = half ? mode1 : mode0;
        if (half < nops && mode) {
            const float* ga = half ? ga1 : ga0;
            const float* be = half ? be1 : be0;
            const float* al = half ? al1 : al0;
            const float* st = half ? st1 : st0;
            float invn = 1.0f / (float)NN;
            float mean = st[c] * invn, e2 = st[128 + c] * invn;
            float a = al[c];
            float var = e2 - mean * mean * a * (2.0f - a);
            float rs = rsqrtf(var + EPSV);
            float g = ga[c];
            aff[half * 256 + c] = g * rs;
            aff[half * 256 + 128 + c] = be[c] - g * rs * a * mean;
        }
    }
    __syncthreads();

    float acc[2][4][4];
#pragma unroll
    for (int mt = 0; mt < 2; mt++)
#pragma unroll
        for (int nt = 0; nt < 4; nt++)
#pragma unroll
            for (int j = 0; j < 4; j++) acc[mt][nt][j] = 0.f;

    const int arow = tid >> 2;           // A staging row 0..63
    const int kq = (tid & 3) * 32;       // A staging k quarter
    const int grow = row0 + arow;

    // ldmatrix per-lane base addresses
    const uint32_t a_lm = sb + A_HI_OFF +
        (uint32_t)(warp_m * 32 + ((lane >> 3) & 1) * 8 + (lane & 7)) * GP +
        (uint32_t)((lane >> 4) & 1) * 16;
    const uint32_t b_lm = sb + B_HI_OFF +
        (uint32_t)(warp_n * 32 + ((lane >> 4) & 1) * 8 + (lane & 7)) * GP +
        (uint32_t)((lane >> 3) & 1) * 16;

    for (int op = 0; op < nops; op++) {
        const float* A = op ? A1 : A0;
        const float* ss = aff + op * 256;
        const float* tt = ss + 128;
        const int mode = op ? mode1 : mode0;
        const int bm = op ? bm1 : bm0;

        if (op > 0) __syncthreads();   // previous op's frags fully consumed

        // ---- stage B hi/lo via cp.async (overlaps with A transform below) ----
        {
            const char* Bh = (const char*)(g_Bhi + (size_t)bm * 16384);
            const char* Bl = (const char*)(g_Blo + (size_t)bm * 16384);
            uint32_t kb = (uint32_t)(tid & 15) * 16;         // byte offset within row
            int rbase = tid >> 4;                             // 0..15
#pragma unroll
            for (int it = 0; it < 8; it++) {
                int goff = (it * 256 + tid) * 16;             // global byte offset
                int rowb = it * 16 + rbase;
                uint32_t soff = (uint32_t)rowb * GP + kb;
                cpa16(sb + B_HI_OFF + soff, Bh + goff);
                cpa16(sb + B_LO_OFF + soff, Bl + goff);
            }
            asm volatile("cp.async.commit_group;" ::: "memory");
        }

        // ---- stage A hi/lo (fused transform + split) ----
#pragma unroll
        for (int c = 0; c < 4; c++) {
            int k0 = kq + c * 8;
            float f[8];
            if (grow < NN) {
                float4 a = *(const float4*)(A + (size_t)grow * HD + k0);
                float4 b = *(const float4*)(A + (size_t)grow * HD + k0 + 4);
                f[0] = a.x; f[1] = a.y; f[2] = a.z; f[3] = a.w;
                f[4] = b.x; f[5] = b.y; f[6] = b.z; f[7] = b.w;
            } else {
#pragma unroll
                for (int j = 0; j < 8; j++) f[j] = 0.f;
            }
            if (mode) {
                float4 sv0 = *(const float4*)(ss + k0);
                float4 sv1 = *(const float4*)(ss + k0 + 4);
                float4 tv0 = *(const float4*)(tt + k0);
                float4 tv1 = *(const float4*)(tt + k0 + 4);
                f[0] = fmaf(f[0], sv0.x, tv0.x); f[1] = fmaf(f[1], sv0.y, tv0.y);
                f[2] = fmaf(f[2], sv0.z, tv0.z); f[3] = fmaf(f[3], sv0.w, tv0.w);
                f[4] = fmaf(f[4], sv1.x, tv1.x); f[5] = fmaf(f[5], sv1.y, tv1.y);
                f[6] = fmaf(f[6], sv1.z, tv1.z); f[7] = fmaf(f[7], sv1.w, tv1.w);
                if (mode == 2) {
#pragma unroll
                    for (int j = 0; j < 8; j++) f[j] = fmaxf(f[j], 0.f);
                }
            }
            float hi[8], lo[8];
#pragma unroll
            for (int j = 0; j < 8; j++) {
                hi[j] = __bfloat162float(__float2bfloat16(f[j]));
                lo[j] = f[j] - hi[j];
            }
            uint32_t off = (uint32_t)arow * GP + (uint32_t)k0 * 2;
            *(uint4*)(smem + A_HI_OFF + off) =
                make_uint4(packbf2(hi[0], hi[1]), packbf2(hi[2], hi[3]),
                           packbf2(hi[4], hi[5]), packbf2(hi[6], hi[7]));
            *(uint4*)(smem + A_LO_OFF + off) =
                make_uint4(packbf2(lo[0], lo[1]), packbf2(lo[2], lo[3]),
                           packbf2(lo[4], lo[5]), packbf2(lo[6], lo[7]));
        }
        asm volatile("cp.async.wait_group 0;" ::: "memory");
        __syncthreads();

        // ---- compute: per k-step, LDSM fragments + 3-term split MMAs ----
#pragma unroll 2
        for (int ks = 0; ks < 8; ks++) {
            const uint32_t k2 = (uint32_t)ks * 32;           // byte offset of k-step
            uint32_t bh[2][4], bl[2][4];
#pragma unroll
            for (int ntp = 0; ntp < 2; ntp++) {
                uint32_t ba = b_lm + (uint32_t)(ntp * 16) * GP + k2;
                ldsm4(bh[ntp], ba);
                ldsm4(bl[ntp], ba + (B_LO_OFF - B_HI_OFF));
            }
            uint32_t ah[2][4], al[2][4];
#pragma unroll
            for (int mt = 0; mt < 2; mt++) {
                uint32_t aa = a_lm + (uint32_t)(mt * 16) * GP + k2;
                ldsm4(ah[mt], aa);
                ldsm4(al[mt], aa + (A_LO_OFF - A_HI_OFF));
            }
            // term 1: Ahi x Bhi (8 independent acc targets)
#pragma unroll
            for (int mt = 0; mt < 2; mt++)
#pragma unroll
                for (int ntp = 0; ntp < 2; ntp++) {
                    mma16816(acc[mt][2 * ntp],     ah[mt], bh[ntp][0], bh[ntp][1]);
                    mma16816(acc[mt][2 * ntp + 1], ah[mt], bh[ntp][2], bh[ntp][3]);
                }
            // term 2: Alo x Bhi
#pragma unroll
            for (int mt = 0; mt < 2; mt++)
#pragma unroll
                for (int ntp = 0; ntp < 2; ntp++) {
                    mma16816(acc[mt][2 * ntp],     al[mt], bh[ntp][0], bh[ntp][1]);
                    mma16816(acc[mt][2 * ntp + 1], al[mt], bh[ntp][2], bh[ntp][3]);
                }
            // term 3: Ahi x Blo
#pragma unroll
            for (int mt = 0; mt < 2; mt++)
#pragma unroll
                for (int ntp = 0; ntp < 2; ntp++) {
                    mma16816(acc[mt][2 * ntp],     ah[mt], bl[ntp][0], bl[ntp][1]);
                    mma16816(acc[mt][2 * ntp + 1], ah[mt], bl[ntp][2], bl[ntp][3]);
                }
        }
    }

    // ---- epilogue: bias, optional relu, store (fp32 or fp16), optional fused stats ----
    float csum[4][2], csq[4][2];
#pragma unroll
    for (int nt = 0; nt < 4; nt++) {
        csum[nt][0] = csum[nt][1] = 0.f;
        csq[nt][0] = csq[nt][1] = 0.f;
    }
#pragma unroll
    for (int mt = 0; mt < 2; mt++) {
        int r0 = row0 + warp_m * 32 + mt * 16 + (lane >> 2);
#pragma unroll
        for (int nt = 0; nt < 4; nt++) {
            int cidx = warp_n * 32 + nt * 8 + (lane & 3) * 2;
            float bx = bias[cidx], by = bias[cidx + 1];
            float v0 = acc[mt][nt][0] + bx, v1 = acc[mt][nt][1] + by;
            float v2 = acc[mt][nt][2] + bx, v3 = acc[mt][nt][3] + by;
            if (epi_relu) {
                v0 = fmaxf(v0, 0.f); v1 = fmaxf(v1, 0.f);
                v2 = fmaxf(v2, 0.f); v3 = fmaxf(v3, 0.f);
            }
            if (statout) {
                if (r0 < NN) {
                    csum[nt][0] += v0; csq[nt][0] = fmaf(v0, v0, csq[nt][0]);
                    csum[nt][1] += v1; csq[nt][1] = fmaf(v1, v1, csq[nt][1]);
                }
                if (r0 + 8 < NN) {
                    csum[nt][0] += v2; csq[nt][0] = fmaf(v2, v2, csq[nt][0]);
                    csum[nt][1] += v3; csq[nt][1] = fmaf(v3, v3, csq[nt][1]);
                }
            }
            if (Ch) {
                if (r0 < NN)
                    *(__half2*)(Ch + (size_t)r0 * HD + cidx) = __floats2half2_rn(v0, v1);
                if (r0 + 8 < NN)
                    *(__half2*)(Ch + (size_t)(r0 + 8) * HD + cidx) = __floats2half2_rn(v2, v3);
            } else {
                if (r0 < NN)
                    *(float2*)(C + (size_t)r0 * HD + cidx) = make_float2(v0, v1);
                if (r0 + 8 < NN)
                    *(float2*)(C + (size_t)(r0 + 8) * HD + cidx) = make_float2(v2, v3);
            }
        }
    }
    if (statout) {
        float* sstat = (float*)(smem + STAT_OFF);
        sstat[tid] = 0.f;
        __syncthreads();
#pragma unroll
        for (int nt = 0; nt < 4; nt++) {
#pragma unroll
            for (int j = 0; j < 2; j++) {
                float s = csum[nt][j], q = csq[nt][j];
                s += __shfl_down_sync(0xffffffffu, s, 16);
                s += __shfl_down_sync(0xffffffffu, s, 8);
                s += __shfl_down_sync(0xffffffffu, s, 4);
                q += __shfl_down_sync(0xffffffffu, q, 16);
                q += __shfl_down_sync(0xffffffffu, q, 8);
                q += __shfl_down_sync(0xffffffffu, q, 4);
                if ((lane >> 2) == 0) {
                    int cidx = warp_n * 32 + nt * 8 + (lane & 3) * 2 + j;
                    atomicAdd(&sstat[cidx], s);
                    atomicAdd(&sstat[128 + cidx], q);
                }
            }
        }
        __syncthreads();
        atomicAdd(&statout[tid], sstat[tid]);
    }
}

// ------------------------- launch -------------------------
extern "C" void kernel_launch(void* const* d_in, const int* in_sizes, int n_in,
                              void* d_out, int out_size) {
    const int*   x_idx = (const int*)d_in[0];
    const int*   erow  = (const int*)d_in[1];
    const int*   ecol  = erow + NE;
    const float* ew    = (const float*)d_in[2];
    const float* emb   = (const float*)d_in[3];
    const float* Wt    = (const float*)d_in[4];
    const float* bt    = (const float*)d_in[5];
    const float* Wc    = (const float*)d_in[6];
    const float* bc    = (const float*)d_in[7];
    const float* cg_g  = (const float*)d_in[8];
    const float* cg_b  = (const float*)d_in[9];
    const float* cg_a  = (const float*)d_in[10];
    const float* gn_g  = (const float*)d_in[11];
    const float* gn_b  = (const float*)d_in[12];
    const float* gn_a  = (const float*)d_in[13];

    void* p;
    cudaGetSymbolAddress(&p, g_B0);   float*  B0 = (float*)p;
    cudaGetSymbolAddress(&p, g_B1);   float*  B1 = (float*)p;
    cudaGetSymbolAddress(&p, g_Hh);   __half* Hb = (__half*)p;
    cudaGetSymbolAddress(&p, g_M);    float*  Mb = (float*)p;
    cudaGetSymbolAddress(&p, g_stat); float*  ST = (float*)p;   // [5][256]

    cudaFuncSetAttribute(gemm_mma, cudaFuncAttributeMaxDynamicSharedMemorySize, GSMEM);

    const int TB = 256;
    const int GB = (NN + 63) / 64;     // 1563 GEMM tiles
    const int F0B = (NN + WCNT + NN * 32 + TB - 1) / TB;
    const float* FN = (const float*)0;
    float* FNo = (float*)0;

    // fork a side stream so the CSR preprocessing chain overlaps gemm1-L0 (R14 schedule)
    cudaStream_t s2;
    cudaStreamCreateWithFlags(&s2, cudaStreamNonBlocking);
    cudaEvent_t ev0, ev1;
    cudaEventCreateWithFlags(&ev0, cudaEventDisableTiming);
    cudaEventCreateWithFlags(&ev1, cudaEventDisableTiming);

    // main: fused0 -> gemm1(L0) ----------------wait(ev1)-> spmm ...
    // side:        \-> hist -> scan1 -> scan3 -> scatter -/
    fused0_kernel<<<F0B, TB>>>(x_idx, emb, Wt, Wc);
    cudaEventRecord(ev0, 0);
    cudaStreamWaitEvent(s2, ev0, 0);
    hist_kernel<<<(NE + TB - 1) / TB, TB, 0, s2>>>(erow);
    scan1_kernel<<<NSCANB, 1024, 0, s2>>>();
    // launch #3 = gemm_mma (profiled): h = relu(x @ Wt[0] + bt[0]) -> fp16
    gemm_mma<<<GB, TB, GSMEM>>>(B0, FN, FN, FN, FN, 0,
                                FN, FN, FN, FN, FN, 0,
                                1, 0, 0, bt, (float*)0, Hb, 1, FNo);
    scan3_kernel<<<(NN + TB - 1) / TB, TB, 0, s2>>>();
    scatter_kernel<<<(NE + TB - 1) / TB, TB, 0, s2>>>(erow, ecol, ew);
    cudaEventRecord(ev1, s2);
    cudaStreamWaitEvent(0, ev1, 0);

    const float* Xcur = B0;
    int modeX = 0;
    for (int i = 0; i < 3; i++) {
        const float* gnst = (i > 0) ? (ST + (3 + i - 1) * 256) : FN;
        const float* gng = (i > 0) ? gn_g + (i - 1) * HD : FN;
        const float* gnb = (i > 0) ? gn_b + (i - 1) * HD : FN;
        const float* gna = (i > 0) ? gn_a + (i - 1) * HD : FN;
        if (i > 0) {
            // h = relu(gn_affine(x) @ Wt[i] + bt[i]) -> fp16
            gemm_mma<<<GB, TB, GSMEM>>>(Xcur, gng, gnb, gna, gnst, modeX,
                                        FN, FN, FN, FN, FN, 0,
                                        1, i, 0, bt + i * HD, (float*)0, Hb, 1, FNo);
        }
        // m = mean-normalized A @ h (CSR, deg computed inline) + fused cg stats
        spmm_kernel<<<SPB2, TB>>>(Hb, Mb, ST + i * 256);
        // out = cg_affine(m) @ Wc[i][:128] + gn_affine(x) @ Wc[i][128:] + bc[i]
        //       (+ fused gn column stats on out for i<2)
        float* Onext = (i == 2) ? (float*)d_out : ((i == 0) ? B1 : B0);
        float* statout = (i < 2) ? (ST + (3 + i) * 256) : FNo;
        gemm_mma<<<GB, TB, GSMEM>>>(Mb, cg_g + i * HD, cg_b + i * HD, cg_a + i * HD,
                                    ST + i * 256, 1,
                                    Xcur, gng, gnb, gna, gnst, modeX,
                                    2, 3 + i * 2, 3 + i * 2 + 1, bc + i * HD,
                                    Onext, (__half*)0, 0, statout);
        if (i < 2) {
            Xcur = Onext;
            modeX = 2;
        }
    }

    cudaEventDestroy(ev0);
    cudaEventDestroy(ev1);
    cudaStreamDestroy(s2);
}